// round 2
// baseline (speedup 1.0000x reference)
#include <cuda_runtime.h>
#include <cstdint>

#define NN   4096
#define EE   4096
#define BB   3
#define DIN  64
#define HID  32
#define WORDS 128          // 4096/32
#define FULLMASK 0xffffffffu

// ---------------- scratch (static device globals; no allocation) ----------------
__device__ uint32_t g_Hb [BB * NN * WORDS];   // row-major bitmask:  bit = H[b][n][e]
__device__ uint32_t g_HbT[BB * EE * WORDS];   // transposed bitmask: bit = H[b][n][e], row = e
__device__ float    g_dv [BB * NN];
__device__ float    g_de [BB * EE];
__device__ float    g_x  [NN * HID];
__device__ float    g_y  [BB * NN * HID];
__device__ float    g_z  [BB * EE * HID];

// ---------------- kernel 1: dense H -> bitmasks ----------------
// block = 1024 threads (32 warps), supertile = 32 rows(n) x 1024 cols(e)
// grid  = BB * (NN/32) * (EE/1024) = 3*128*4 = 1536
__global__ __launch_bounds__(1024) void k_pack(const float* __restrict__ H) {
    __shared__ uint32_t sA[32][33];
    const int w    = threadIdx.x >> 5;
    const int lane = threadIdx.x & 31;

    const int bid = blockIdx.x;
    const int b   = bid >> 9;          // / 512
    const int r   = bid & 511;
    const int tn  = r >> 2;            // n-tile (32 rows)
    const int se  = r & 3;             // e-supertile (1024 cols)
    const int n0  = tn * 32;
    const int e0  = se * 1024 + w * 32;    // this warp's 32-column slab

    const float* Hp = H + ((size_t)b * NN + n0) * EE + e0 + lane;

    uint32_t rw = 0;                   // lane i ends up holding row word for row n0+i
    #pragma unroll
    for (int half = 0; half < 2; half++) {
        float v[16];
        #pragma unroll
        for (int i = 0; i < 16; i++)
            v[i] = Hp[(size_t)(half * 16 + i) * EE];
        #pragma unroll
        for (int i = 0; i < 16; i++) {
            unsigned bal = __ballot_sync(FULLMASK, v[i] != 0.0f);
            if (lane == half * 16 + i) rw = bal;
        }
    }

    // stage for coalesced Hbits write
    sA[lane][w] = rw;

    // 32x32 bit transpose: lane j gets word whose bit i = H[b][n0+i][e0+j]
    uint32_t tw = 0;
    #pragma unroll
    for (int j = 0; j < 32; j++) {
        unsigned bal = __ballot_sync(FULLMASK, (rw >> j) & 1u);
        if (lane == j) tw = bal;
    }
    // HbT row = e0+lane, word index = tn   (scattered 4B stores; 6MB total payload)
    g_HbT[((size_t)b * EE + e0 + lane) * WORDS + tn] = tw;

    __syncthreads();
    // coalesced Hbits write: warp w writes row n0+w, words [se*32, se*32+32)
    g_Hb[((size_t)b * NN + n0 + w) * WORDS + se * 32 + lane] = sA[w][lane];
}

// ---------------- kernel 2: degree normalizers ----------------
// one warp per row; first BB*NN warps -> dv (from g_Hb), next BB*EE -> de (from g_HbT)
// total warps = BB*(NN+EE) = 24576  ->  768 blocks of 1024 threads
__global__ __launch_bounds__(1024) void k_deg() {
    const int gw   = (blockIdx.x * blockDim.x + threadIdx.x) >> 5;
    const int lane = threadIdx.x & 31;

    const uint32_t* src;
    int row;
    bool isdv;
    if (gw < BB * NN) { src = g_Hb;  row = gw;           isdv = true;  }
    else              { src = g_HbT; row = gw - BB * NN; isdv = false; }

    const uint32_t* p = src + (size_t)row * WORDS;
    int cnt = 0;
    #pragma unroll
    for (int k = 0; k < 4; k++) cnt += __popc(p[lane + 32 * k]);
    #pragma unroll
    for (int o = 16; o; o >>= 1) cnt += __shfl_xor_sync(FULLMASK, cnt, o);

    if (lane == 0) {
        float d = fmaxf((float)cnt, 1e-6f);
        if (isdv) g_dv[row] = rsqrtf(d);
        else      g_de[row] = 1.0f / d;
    }
}

// ---------------- kernel 3: x = relu(X @ W_init + b_init) ----------------
__global__ __launch_bounds__(256) void k_init(const float* __restrict__ X,
                                              const float* __restrict__ Wi,
                                              const float* __restrict__ bi) {
    __shared__ float Ws[DIN * HID];
    for (int i = threadIdx.x; i < DIN * HID; i += 256) Ws[i] = Wi[i];
    __syncthreads();

    const int warp = threadIdx.x >> 5, lane = threadIdx.x & 31;
    const int n = blockIdx.x * 8 + warp;

    const float xv0 = X[(size_t)n * DIN + lane];
    const float xv1 = X[(size_t)n * DIN + 32 + lane];
    float acc = bi[lane];
    #pragma unroll
    for (int d = 0; d < 32; d++)
        acc += __shfl_sync(FULLMASK, xv0, d) * Ws[d * HID + lane];
    #pragma unroll
    for (int d = 0; d < 32; d++)
        acc += __shfl_sync(FULLMASK, xv1, d) * Ws[(32 + d) * HID + lane];

    g_x[n * HID + lane] = fmaxf(acc, 0.0f);
}

// ---------------- kernel 4a: xw = x@W_node[l]+b ; y[b] = dv[b]*xw ----------------
__global__ __launch_bounds__(256) void k_xwy(const float* __restrict__ Wn,
                                             const float* __restrict__ bn) {
    __shared__ float Ws[HID * HID];
    for (int i = threadIdx.x; i < HID * HID; i += 256) Ws[i] = Wn[i];
    __syncthreads();

    const int warp = threadIdx.x >> 5, lane = threadIdx.x & 31;
    const int n = blockIdx.x * 8 + warp;

    const float xv = g_x[n * HID + lane];
    float acc = bn[lane];
    #pragma unroll
    for (int g = 0; g < 32; g++)
        acc += __shfl_sync(FULLMASK, xv, g) * Ws[g * HID + lane];

    #pragma unroll
    for (int b = 0; b < BB; b++)
        g_y[((size_t)b * NN + n) * HID + lane] = g_dv[b * NN + n] * acc;
}

// gather sum of feature rows selected by a 4096-bit row of a bitmask
__device__ __forceinline__ float gather_rows(const uint32_t* __restrict__ hp,
                                             const float* __restrict__ base,
                                             int lane) {
    uint32_t wb[4];
    #pragma unroll
    for (int k = 0; k < 4; k++) wb[k] = hp[lane + 32 * k];
    float acc = 0.0f;
    #pragma unroll
    for (int k = 0; k < 4; k++) {
        for (int s = 0; s < 32; s++) {
            uint32_t wd = __shfl_sync(FULLMASK, wb[k], s);   // warp-uniform
            if (wd) {
                const int rb = (k * 32 + s) * 32;
                do {
                    const int i = __ffs(wd) - 1;
                    wd &= wd - 1;
                    acc += base[(size_t)(rb + i) * HID + lane];  // coalesced 128B row
                } while (wd);
            }
        }
    }
    return acc;
}

// ---------------- kernel 4b: z[b,e,:] = de * sum_{n in col e} y[b,n,:] ----------------
// one warp per (b,e): 12288 warps
__global__ __launch_bounds__(256) void k_z() {
    const int gw   = (blockIdx.x * 256 + threadIdx.x) >> 5;   // = b*EE + e
    const int lane = threadIdx.x & 31;
    const int b    = gw >> 12;

    const float acc = gather_rows(g_HbT + (size_t)gw * WORDS,
                                  g_y + (size_t)b * NN * HID, lane);
    g_z[(size_t)gw * HID + lane] = g_de[gw] * acc;
}

// ---------------- kernel 4c: u -> msg -> weighted combine -> relu -> x ----------------
// one warp per node
__global__ __launch_bounds__(256) void k_umsg(const float* __restrict__ Theta,
                                              const float* __restrict__ bimp) {
    __shared__ float Th[BB * HID * HID];   // premultiplied by softmax weight
    {
        const float i0 = bimp[0], i1 = bimp[1], i2 = bimp[2];
        const float m  = fmaxf(i0, fmaxf(i1, i2));
        const float x0 = __expf(i0 - m), x1 = __expf(i1 - m), x2 = __expf(i2 - m);
        const float inv = 1.0f / (x0 + x1 + x2);
        const float wv0 = x0 * inv, wv1 = x1 * inv, wv2 = x2 * inv;
        for (int i = threadIdx.x; i < BB * HID * HID; i += 256) {
            const int bb = i >> 10;
            const float wv = (bb == 0) ? wv0 : (bb == 1) ? wv1 : wv2;
            Th[i] = Theta[i] * wv;
        }
    }
    __syncthreads();

    const int warp = threadIdx.x >> 5, lane = threadIdx.x & 31;
    const int n = blockIdx.x * 8 + warp;

    float acc = 0.0f;
    #pragma unroll
    for (int b = 0; b < BB; b++) {
        float ub = gather_rows(g_Hb + ((size_t)b * NN + n) * WORDS,
                               g_z + (size_t)b * EE * HID, lane);
        ub *= g_dv[b * NN + n];
        #pragma unroll
        for (int h = 0; h < 32; h++) {
            const float uv = __shfl_sync(FULLMASK, ub, h);
            acc += uv * Th[b * HID * HID + h * HID + lane];
        }
    }
    g_x[n * HID + lane] = fmaxf(acc, 0.0f);
}

// ---------------- kernel 5: out = relu(x@Wp1+bp1)@Wp2+bp2 ----------------
__global__ __launch_bounds__(256) void k_proj(const float* __restrict__ Wp1,
                                              const float* __restrict__ bp1,
                                              const float* __restrict__ Wp2,
                                              const float* __restrict__ bp2,
                                              float* __restrict__ out) {
    __shared__ float W1[HID * HID], W2[HID * HID];
    for (int i = threadIdx.x; i < HID * HID; i += 256) { W1[i] = Wp1[i]; W2[i] = Wp2[i]; }
    __syncthreads();

    const int warp = threadIdx.x >> 5, lane = threadIdx.x & 31;
    const int n = blockIdx.x * 8 + warp;

    const float xv = g_x[n * HID + lane];
    float h = bp1[lane];
    #pragma unroll
    for (int g = 0; g < 32; g++)
        h += __shfl_sync(FULLMASK, xv, g) * W1[g * HID + lane];
    h = fmaxf(h, 0.0f);

    float o = bp2[lane];
    #pragma unroll
    for (int g = 0; g < 32; g++)
        o += __shfl_sync(FULLMASK, h, g) * W2[g * HID + lane];

    out[(size_t)n * HID + lane] = o;
}

// ---------------- launcher ----------------
extern "C" void kernel_launch(void* const* d_in, const int* in_sizes, int n_in,
                              void* d_out, int out_size) {
    const float* X    = (const float*)d_in[0];
    const float* H    = (const float*)d_in[1];
    const float* Wi   = (const float*)d_in[2];
    const float* bi   = (const float*)d_in[3];
    const float* Wn   = (const float*)d_in[4];   // [2,32,32]
    const float* bn   = (const float*)d_in[5];   // [2,32]
    const float* Th   = (const float*)d_in[6];   // [3,32,32]
    const float* bimp = (const float*)d_in[7];   // [3]
    const float* Wp1  = (const float*)d_in[8];
    const float* bp1  = (const float*)d_in[9];
    const float* Wp2  = (const float*)d_in[10];
    const float* bp2  = (const float*)d_in[11];
    float* out = (float*)d_out;

    k_pack<<<BB * (NN / 32) * (EE / 1024), 1024>>>(H);
    // BB*(NN+EE) = 24576 warps @ 32 warps/block -> 768 blocks   (R1 bug: was 24)
    k_deg<<<BB * (NN + EE) / 32, 1024>>>();
    k_init<<<NN / 8, 256>>>(X, Wi, bi);

    for (int l = 0; l < 2; l++) {
        k_xwy<<<NN / 8, 256>>>(Wn + l * HID * HID, bn + l * HID);
        k_z<<<(BB * EE) / 8, 256>>>();                      // 12288 warps -> 1536 blocks
        k_umsg<<<NN / 8, 256>>>(Th, bimp);
    }

    k_proj<<<NN / 8, 256>>>(Wp1, bp1, Wp2, bp2, out);
}

// round 3
// speedup vs baseline: 1.7597x; 1.7597x over previous
#include <cuda_runtime.h>
#include <cstdint>

#define NN   4096
#define EE   4096
#define BB   3
#define DIN  64
#define HID  32
#define WORDS 128          // 4096/32
#define CAP  128           // padded adjacency capacity (deg mean 32.8, >11 sigma safe)
#define FM   0xffffffffu

// ---------------- scratch (static device globals) ----------------
__device__ uint32_t g_Hb  [BB * NN * WORDS];   // bit = H[b][n][e], row-major n
__device__ uint32_t g_HbT [BB * EE * WORDS];   // bit = H[b][n][e], row-major e
__device__ uint16_t g_rIdx[BB * NN * CAP];     // edges incident to node n
__device__ uint16_t g_cIdx[BB * EE * CAP];     // nodes incident to edge e
__device__ int      g_degN[BB * NN];
__device__ int      g_degE[BB * EE];
__device__ float    g_dv  [BB * NN];
__device__ float    g_de  [BB * EE];
__device__ float    g_y   [BB * NN * HID];
__device__ float    g_z   [BB * EE * HID];

// ---------------- kernel 1: dense H -> bitmasks ----------------
// block = 1024 threads (32 warps), supertile = 32 rows x 1024 cols
__global__ __launch_bounds__(1024) void k_pack(const float* __restrict__ H) {
    __shared__ uint32_t sA[32][33];
    const int w    = threadIdx.x >> 5;
    const int lane = threadIdx.x & 31;

    const int bid = blockIdx.x;
    const int b   = bid >> 9;
    const int r   = bid & 511;
    const int tn  = r >> 2;            // n-tile (32 rows)
    const int se  = r & 3;             // e-supertile (1024 cols)
    const int n0  = tn * 32;
    const int e0  = se * 1024 + w * 32;

    const float* Hp = H + ((size_t)b * NN + n0) * EE + e0 + lane;

    uint32_t rw = 0;                   // lane i holds row word for row n0+i
    #pragma unroll
    for (int half = 0; half < 2; half++) {
        float v[16];
        #pragma unroll
        for (int i = 0; i < 16; i++)
            v[i] = Hp[(size_t)(half * 16 + i) * EE];
        #pragma unroll
        for (int i = 0; i < 16; i++) {
            unsigned bal = __ballot_sync(FM, v[i] != 0.0f);
            if (lane == half * 16 + i) rw = bal;
        }
    }

    sA[lane][w] = rw;

    // 32x32 bit transpose
    uint32_t tw = 0;
    #pragma unroll
    for (int j = 0; j < 32; j++) {
        unsigned bal = __ballot_sync(FM, (rw >> j) & 1u);
        if (lane == j) tw = bal;
    }
    g_HbT[((size_t)b * EE + e0 + lane) * WORDS + tn] = tw;

    __syncthreads();
    g_Hb[((size_t)b * NN + n0 + w) * WORDS + se * 32 + lane] = sA[w][lane];
}

// ---------------- kernel 2: bitmask -> padded CSR + degrees + normalizers ----
// one warp per row; node rows [0, BB*NN), edge rows [BB*NN, BB*(NN+EE))
// grid = 24576 warps / 32 = 768 blocks
__global__ __launch_bounds__(1024) void k_fill() {
    const int gw   = (blockIdx.x * 1024 + threadIdx.x) >> 5;
    const int lane = threadIdx.x & 31;
    const bool nodeSide = gw < BB * NN;
    const int row = nodeSide ? gw : gw - BB * NN;

    const uint32_t* p = (nodeSide ? g_Hb : g_HbT) + (size_t)row * WORDS;
    const uint4 v = ((const uint4*)p)[lane];       // words lane*4 .. lane*4+3
    uint32_t ws[4] = {v.x, v.y, v.z, v.w};

    const int t = __popc(ws[0]) + __popc(ws[1]) + __popc(ws[2]) + __popc(ws[3]);
    int s = t;                                      // inclusive warp scan
    #pragma unroll
    for (int o = 1; o < 32; o <<= 1) {
        int u = __shfl_up_sync(FM, s, o);
        if (lane >= o) s += u;
    }
    const int total = __shfl_sync(FM, s, 31);
    int slot = s - t;                               // exclusive prefix

    uint16_t* out = (nodeSide ? g_rIdx : g_cIdx) + (size_t)row * CAP;
    #pragma unroll
    for (int k = 0; k < 4; k++) {
        uint32_t wd = ws[k];
        const int base = (lane * 4 + k) * 32;
        while (wd) {
            const int i = __ffs(wd) - 1;
            wd &= wd - 1;
            if (slot < CAP) out[slot] = (uint16_t)(base + i);
            slot++;
        }
    }

    if (lane == 0) {
        const float d = fmaxf((float)total, 1e-6f);
        if (nodeSide) { g_degN[row] = min(total, CAP); g_dv[row] = rsqrtf(d); }
        else          { g_degE[row] = min(total, CAP); g_de[row] = 1.0f / d; }
    }
}

// ---------------- helpers ----------------
// indexed gather-sum of feature rows, 4-way MLP
__device__ __forceinline__ float gather(const uint16_t* __restrict__ idx, int deg,
                                        const float* __restrict__ base, int lane) {
    float a0 = 0.f, a1 = 0.f, a2 = 0.f, a3 = 0.f;
    for (int c = 0; c < deg; c += 32) {
        const int my = idx[c + lane];              // coalesced; padded row -> safe
        int m = deg - c; if (m > 32) m = 32;
        int j = 0;
        for (; j + 4 <= m; j += 4) {
            const int t0 = __shfl_sync(FM, my, j);
            const int t1 = __shfl_sync(FM, my, j + 1);
            const int t2 = __shfl_sync(FM, my, j + 2);
            const int t3 = __shfl_sync(FM, my, j + 3);
            a0 += base[t0 * HID + lane];
            a1 += base[t1 * HID + lane];
            a2 += base[t2 * HID + lane];
            a3 += base[t3 * HID + lane];
        }
        for (; j < m; j++)
            a0 += base[__shfl_sync(FM, my, j) * HID + lane];
    }
    return (a0 + a1) + (a2 + a3);
}

// out[lane] = bias + sum_g xv(g) * Ws[g][lane], 4 split accumulators
__device__ __forceinline__ float gemm32(float xv, const float* __restrict__ Ws,
                                        float bias, int lane) {
    float a0 = bias, a1 = 0.f, a2 = 0.f, a3 = 0.f;
    #pragma unroll
    for (int g = 0; g < 32; g += 4) {
        a0 += __shfl_sync(FM, xv, g)     * Ws[g * HID + lane];
        a1 += __shfl_sync(FM, xv, g + 1) * Ws[(g + 1) * HID + lane];
        a2 += __shfl_sync(FM, xv, g + 2) * Ws[(g + 2) * HID + lane];
        a3 += __shfl_sync(FM, xv, g + 3) * Ws[(g + 3) * HID + lane];
    }
    return (a0 + a1) + (a2 + a3);
}

__device__ __forceinline__ void softmax3_premul(const float* __restrict__ Theta,
                                                const float* __restrict__ bimp,
                                                float* Th /*smem BB*HID*HID*/) {
    const float i0 = bimp[0], i1 = bimp[1], i2 = bimp[2];
    const float m  = fmaxf(i0, fmaxf(i1, i2));
    const float x0 = __expf(i0 - m), x1 = __expf(i1 - m), x2 = __expf(i2 - m);
    const float inv = 1.0f / (x0 + x1 + x2);
    const float wv[3] = {x0 * inv, x1 * inv, x2 * inv};
    for (int i = threadIdx.x; i < BB * HID * HID; i += 256)
        Th[i] = Theta[i] * wv[i >> 10];
}

// ---------------- kernel 3: y0 = dv * (relu(X@Wi+bi)@Wn0 + bn0) ----------------
__global__ __launch_bounds__(256) void k_init_y(const float* __restrict__ X,
                                                const float* __restrict__ Wi,
                                                const float* __restrict__ bi,
                                                const float* __restrict__ Wn,
                                                const float* __restrict__ bn) {
    __shared__ float sWi[DIN * HID], sWn[HID * HID];
    for (int i = threadIdx.x; i < DIN * HID; i += 256) sWi[i] = Wi[i];
    for (int i = threadIdx.x; i < HID * HID; i += 256) sWn[i] = Wn[i];
    __syncthreads();

    const int warp = threadIdx.x >> 5, lane = threadIdx.x & 31;
    const int n = blockIdx.x * 8 + warp;

    const float x0v = X[(size_t)n * DIN + lane];
    const float x1v = X[(size_t)n * DIN + 32 + lane];

    float a0 = bi[lane], a1 = 0.f, a2 = 0.f, a3 = 0.f;
    #pragma unroll
    for (int g = 0; g < 32; g += 4) {
        a0 += __shfl_sync(FM, x0v, g)     * sWi[g * HID + lane];
        a1 += __shfl_sync(FM, x0v, g + 1) * sWi[(g + 1) * HID + lane];
        a2 += __shfl_sync(FM, x0v, g + 2) * sWi[(g + 2) * HID + lane];
        a3 += __shfl_sync(FM, x0v, g + 3) * sWi[(g + 3) * HID + lane];
    }
    #pragma unroll
    for (int g = 0; g < 32; g += 4) {
        a0 += __shfl_sync(FM, x1v, g)     * sWi[(32 + g) * HID + lane];
        a1 += __shfl_sync(FM, x1v, g + 1) * sWi[(33 + g) * HID + lane];
        a2 += __shfl_sync(FM, x1v, g + 2) * sWi[(34 + g) * HID + lane];
        a3 += __shfl_sync(FM, x1v, g + 3) * sWi[(35 + g) * HID + lane];
    }
    const float x  = fmaxf((a0 + a1) + (a2 + a3), 0.0f);
    const float xw = gemm32(x, sWn, bn[lane], lane);

    #pragma unroll
    for (int b = 0; b < BB; b++)
        g_y[((size_t)b * NN + n) * HID + lane] = g_dv[b * NN + n] * xw;
}

// ---------------- kernel 4: z[b,e] = de * sum_{n in e} y[b,n] ----------------
__global__ __launch_bounds__(256) void k_z() {
    const int gw   = (blockIdx.x * 256 + threadIdx.x) >> 5;   // = b*EE + e
    const int lane = threadIdx.x & 31;
    const int b    = gw >> 12;

    const float acc = gather(g_cIdx + (size_t)gw * CAP, g_degE[gw],
                             g_y + (size_t)b * NN * HID, lane);
    g_z[(size_t)gw * HID + lane] = g_de[gw] * acc;
}

// ---------------- kernel 5: umsg (layer l) + next-layer xwy -> y ----------------
__global__ __launch_bounds__(256) void k_mid(const float* __restrict__ Theta,
                                             const float* __restrict__ bimp,
                                             const float* __restrict__ Wn,
                                             const float* __restrict__ bn) {
    __shared__ float Th[BB * HID * HID], sWn[HID * HID];
    softmax3_premul(Theta, bimp, Th);
    for (int i = threadIdx.x; i < HID * HID; i += 256) sWn[i] = Wn[i];
    __syncthreads();

    const int warp = threadIdx.x >> 5, lane = threadIdx.x & 31;
    const int n = blockIdx.x * 8 + warp;

    float c0 = 0.f, c1 = 0.f, c2 = 0.f, c3 = 0.f;
    #pragma unroll
    for (int b = 0; b < BB; b++) {
        const int rn = b * NN + n;
        const float ub = gather(g_rIdx + (size_t)rn * CAP, g_degN[rn],
                                g_z + (size_t)b * EE * HID, lane) * g_dv[rn];
        const float* T = Th + b * HID * HID;
        #pragma unroll
        for (int h = 0; h < 32; h += 4) {
            c0 += __shfl_sync(FM, ub, h)     * T[h * HID + lane];
            c1 += __shfl_sync(FM, ub, h + 1) * T[(h + 1) * HID + lane];
            c2 += __shfl_sync(FM, ub, h + 2) * T[(h + 2) * HID + lane];
            c3 += __shfl_sync(FM, ub, h + 3) * T[(h + 3) * HID + lane];
        }
    }
    const float x  = fmaxf((c0 + c1) + (c2 + c3), 0.0f);
    const float xw = gemm32(x, sWn, bn[lane], lane);

    #pragma unroll
    for (int b = 0; b < BB; b++)
        g_y[((size_t)b * NN + n) * HID + lane] = g_dv[b * NN + n] * xw;
}

// ---------------- kernel 6: umsg (last layer) + projection MLP -> out ----------
__global__ __launch_bounds__(256) void k_last(const float* __restrict__ Theta,
                                              const float* __restrict__ bimp,
                                              const float* __restrict__ Wp1,
                                              const float* __restrict__ bp1,
                                              const float* __restrict__ Wp2,
                                              const float* __restrict__ bp2,
                                              float* __restrict__ out) {
    __shared__ float Th[BB * HID * HID], sW1[HID * HID], sW2[HID * HID];
    softmax3_premul(Theta, bimp, Th);
    for (int i = threadIdx.x; i < HID * HID; i += 256) { sW1[i] = Wp1[i]; sW2[i] = Wp2[i]; }
    __syncthreads();

    const int warp = threadIdx.x >> 5, lane = threadIdx.x & 31;
    const int n = blockIdx.x * 8 + warp;

    float c0 = 0.f, c1 = 0.f, c2 = 0.f, c3 = 0.f;
    #pragma unroll
    for (int b = 0; b < BB; b++) {
        const int rn = b * NN + n;
        const float ub = gather(g_rIdx + (size_t)rn * CAP, g_degN[rn],
                                g_z + (size_t)b * EE * HID, lane) * g_dv[rn];
        const float* T = Th + b * HID * HID;
        #pragma unroll
        for (int h = 0; h < 32; h += 4) {
            c0 += __shfl_sync(FM, ub, h)     * T[h * HID + lane];
            c1 += __shfl_sync(FM, ub, h + 1) * T[(h + 1) * HID + lane];
            c2 += __shfl_sync(FM, ub, h + 2) * T[(h + 2) * HID + lane];
            c3 += __shfl_sync(FM, ub, h + 3) * T[(h + 3) * HID + lane];
        }
    }
    const float x = fmaxf((c0 + c1) + (c2 + c3), 0.0f);
    const float h = fmaxf(gemm32(x, sW1, bp1[lane], lane), 0.0f);
    const float o = gemm32(h, sW2, bp2[lane], lane);

    out[(size_t)n * HID + lane] = o;   // OUT == HID == 32
}

// ---------------- launcher ----------------
extern "C" void kernel_launch(void* const* d_in, const int* in_sizes, int n_in,
                              void* d_out, int out_size) {
    const float* X    = (const float*)d_in[0];
    const float* H    = (const float*)d_in[1];
    const float* Wi   = (const float*)d_in[2];
    const float* bi   = (const float*)d_in[3];
    const float* Wn   = (const float*)d_in[4];   // [2,32,32]
    const float* bn   = (const float*)d_in[5];   // [2,32]
    const float* Th   = (const float*)d_in[6];   // [3,32,32]
    const float* bimp = (const float*)d_in[7];   // [3]
    const float* Wp1  = (const float*)d_in[8];
    const float* bp1  = (const float*)d_in[9];
    const float* Wp2  = (const float*)d_in[10];
    const float* bp2  = (const float*)d_in[11];
    float* out = (float*)d_out;

    k_pack<<<BB * (NN / 32) * (EE / 1024), 1024>>>(H);          // 1536 blocks
    k_fill<<<BB * (NN + EE) / 32, 1024>>>();                    // 768 blocks
    k_init_y<<<NN / 8, 256>>>(X, Wi, bi, Wn, bn);               // layer 0 node W
    k_z<<<(BB * EE) / 8, 256>>>();
    k_mid<<<NN / 8, 256>>>(Th, bimp, Wn + HID * HID, bn + HID); // layer 1 node W
    k_z<<<(BB * EE) / 8, 256>>>();
    k_last<<<NN / 8, 256>>>(Th, bimp, Wp1, bp1, Wp2, bp2, out);
}